// round 15
// baseline (speedup 1.0000x reference)
#include <cuda_runtime.h>
#include <cuda_fp16.h>
#include <cstdint>
#include <math.h>

#define BATCH   4
#define LSEQ    4096
#define M_TOTAL (BATCH * LSEQ)   // 16384
#define DM      1024
#define EE      2048             // E
#define N1      (2 * EE)         // 4096
#define DSTATE  16
#define DCONV   4

#define KP1 DM                   // 1024  fp16 single-pass GEMM1
#define KP2 EE                   // 2048  fp16 single-pass GEMM2

// -------- scratch (device globals: allocation-free rule) --------
__device__ __half g_xp[M_TOTAL * (size_t)EE];     // 64 MB  x_proj (fp16)
__device__ __half g_zp[M_TOTAL * (size_t)EE];     // 64 MB  z (fp16)
__device__ __half g_xconv[M_TOTAL * (size_t)EE];  // 64 MB  (fp16)
__device__ float  g_u[M_TOTAL * DSTATE];          // 1 MB
__device__ float  g_h[M_TOTAL * DSTATE];          // 1 MB
__device__ __half g_xs[M_TOTAL * (size_t)KP1];    // 32 MB  A for GEMM1
__device__ __half g_w1[(size_t)N1 * KP1];         // 8 MB   B for GEMM1
__device__ __half g_gs[M_TOTAL * (size_t)KP2];    // 64 MB  A for GEMM2
__device__ __half g_w2[(size_t)DM * KP2];         // 4 MB   B for GEMM2

// ============================================================
// helpers
// ============================================================
__device__ __forceinline__ uint32_t smem_u32(const void* p) {
    uint32_t a;
    asm("{ .reg .u64 t; cvta.to.shared.u64 t, %1; cvt.u32.u64 %0, t; }"
        : "=r"(a) : "l"(p));
    return a;
}

#define CP_ASYNC_16(dst_u32, src_ptr) \
    asm volatile("cp.async.cg.shared.global [%0], [%1], 16;" \
                 :: "r"(dst_u32), "l"(src_ptr) : "memory")
#define CP_ASYNC_COMMIT() asm volatile("cp.async.commit_group;" ::: "memory")
#define CP_ASYNC_WAIT1()  asm volatile("cp.async.wait_group 1;" ::: "memory")

__device__ __forceinline__ void ldm_x4(uint32_t& r0, uint32_t& r1,
                                       uint32_t& r2, uint32_t& r3, uint32_t addr) {
    asm volatile("ldmatrix.sync.aligned.m8n8.x4.shared.b16 {%0,%1,%2,%3}, [%4];"
                 : "=r"(r0), "=r"(r1), "=r"(r2), "=r"(r3) : "r"(addr));
}
__device__ __forceinline__ void mma_f16(float* d, const uint32_t* a,
                                        const uint32_t* b) {
    asm volatile(
        "mma.sync.aligned.m16n8k16.row.col.f32.f16.f16.f32 "
        "{%0,%1,%2,%3}, {%4,%5,%6,%7}, {%8,%9}, {%0,%1,%2,%3};"
        : "+f"(d[0]), "+f"(d[1]), "+f"(d[2]), "+f"(d[3])
        : "r"(a[0]), "r"(a[1]), "r"(a[2]), "r"(a[3]), "r"(b[0]), "r"(b[1]));
}

// load/store 4 consecutive halves as float4
__device__ __forceinline__ float4 ld4h(const __half* p) {
    const uint2 raw = *(const uint2*)p;
    const float2 a = __half22float2(*(const __half2*)&raw.x);
    const float2 b = __half22float2(*(const __half2*)&raw.y);
    return make_float4(a.x, a.y, b.x, b.y);
}
__device__ __forceinline__ void st4h(__half* p, float4 v) {
    uint2 raw;
    *(__half2*)&raw.x = __floats2half2_rn(v.x, v.y);
    *(__half2*)&raw.y = __floats2half2_rn(v.z, v.w);
    *(uint2*)p = raw;
}

// ============================================================
// fp16 mma.sync GEMM: C = A[M,KP] @ B[N,KP]^T + bias[N]
// 128x128 CTA tile, BK=64, 8 warps (warp tile 64m x 32n),
// 3-stage cp.async pipeline, XOR-swizzled 128B rows.
// mode 0: fp32 C [M,N] (stride N)
// mode 1: fp16 outputs, cols < EE -> C, cols >= EE -> C2 (stride EE)
// ============================================================
#define TBM 128
#define TBN 128
#define TBK 64
#define ROWB 128                             // bytes per smem row (64 fp16)
#define STAGE_A_BYTES (TBM * ROWB)           // 16384
#define STAGE_BYTES   (2 * STAGE_A_BYTES)    // 32768 (A then B)
#define NSTAGE 3
#define MM_SMEM_BYTES (NSTAGE * STAGE_BYTES) // 98304

__device__ __forceinline__ uint32_t swz(int row, int g) {
    return (uint32_t)(row * ROWB) + (uint32_t)((g ^ (row & 7)) << 4);
}

__global__ __launch_bounds__(256, 2) void mm_gemm(
    const __half* __restrict__ A,
    const __half* __restrict__ B,
    const float* __restrict__ bias,
    void* __restrict__ Cv,
    void* __restrict__ C2v,
    int N, int KP, int mode)
{
    extern __shared__ char dynsmem[];
    const uint32_t sbase = smem_u32(dynsmem);

    const int tid = threadIdx.x;
    const int wid = tid >> 5;
    const int lane = tid & 31;
    const int bm = blockIdx.y * TBM;
    const int bn = blockIdx.x * TBN;

    const int wm = (wid & 1) * 64;   // warp m-offset in tile
    const int wn = (wid >> 1) * 32;  // warp n-offset in tile

    // ---- global->shared mapping
    const int grow = tid >> 1;             // 0..127
    const int gg0 = (tid & 1) * 4;         // 0 or 4
    const __half* Agl = A + (size_t)(bm + grow) * KP + gg0 * 8;
    const __half* Bgl = B + (size_t)(bn + grow) * KP + gg0 * 8;
    uint32_t gdst[4];
#pragma unroll
    for (int i = 0; i < 4; i++) gdst[i] = swz(grow, gg0 + i);

    uint32_t sA[NSTAGE], sB[NSTAGE];
#pragma unroll
    for (int s = 0; s < NSTAGE; s++) {
        sA[s] = sbase + s * STAGE_BYTES;
        sB[s] = sA[s] + STAGE_A_BYTES;
    }

    float acc[4][4][4];
#pragma unroll
    for (int i = 0; i < 4; i++)
#pragma unroll
        for (int j = 0; j < 4; j++)
#pragma unroll
            for (int k = 0; k < 4; k++) acc[i][j][k] = 0.f;

    // ---- ldmatrix per-thread bases
    const int arow = wm + (lane & 15);
    const int axor = arow & 7;
    const int agl = lane >> 4;
    const int brow = wn + (lane & 7) + ((lane >> 4) << 3);
    const int bxor = brow & 7;
    const int bgl = (lane >> 3) & 1;

    const int nchunk = KP / TBK;

    // prologue
#pragma unroll
    for (int s = 0; s < NSTAGE - 1; s++) {
        const size_t koff = (size_t)s * TBK;
#pragma unroll
        for (int i = 0; i < 4; i++) {
            CP_ASYNC_16(sA[s] + gdst[i], Agl + koff + i * 8);
            CP_ASYNC_16(sB[s] + gdst[i], Bgl + koff + i * 8);
        }
        CP_ASYNC_COMMIT();
    }

    int buf = 0, nbuf = NSTAGE - 1;
    for (int c = 0; c < nchunk; c++) {
        CP_ASYNC_WAIT1();
        __syncthreads();

        if (c + NSTAGE - 1 < nchunk) {
            const size_t koff = (size_t)(c + NSTAGE - 1) * TBK;
#pragma unroll
            for (int i = 0; i < 4; i++) {
                CP_ASYNC_16(sA[nbuf] + gdst[i], Agl + koff + i * 8);
                CP_ASYNC_16(sB[nbuf] + gdst[i], Bgl + koff + i * 8);
            }
        }
        CP_ASYNC_COMMIT();

#pragma unroll
        for (int ks = 0; ks < 4; ks++) {
            uint32_t af[4][4], bfr[4][2];
#pragma unroll
            for (int mf = 0; mf < 4; mf++) {
                const int row = arow + mf * 16;
                const uint32_t addr =
                    sA[buf] + row * ROWB + (((ks * 2 + agl) ^ axor) << 4);
                ldm_x4(af[mf][0], af[mf][1], af[mf][2], af[mf][3], addr);
            }
#pragma unroll
            for (int nfp = 0; nfp < 2; nfp++) {
                const int row = brow + nfp * 16;
                const uint32_t addr =
                    sB[buf] + row * ROWB + (((ks * 2 + bgl) ^ bxor) << 4);
                ldm_x4(bfr[nfp * 2][0], bfr[nfp * 2][1],
                       bfr[nfp * 2 + 1][0], bfr[nfp * 2 + 1][1], addr);
            }
#pragma unroll
            for (int mf = 0; mf < 4; mf++)
#pragma unroll
                for (int nf = 0; nf < 4; nf++)
                    mma_f16(acc[mf][nf], af[mf], bfr[nf]);
        }

        buf = (buf + 1 == NSTAGE) ? 0 : buf + 1;
        nbuf = (nbuf + 1 == NSTAGE) ? 0 : nbuf + 1;
    }

    // epilogue
    const int erow = bm + wm + (lane >> 2);
    const int ecol = bn + wn + (lane & 3) * 2;

    if (mode == 1) {
        // fp16 outputs, split at column EE, stride EE
        __half* Hb = (bn < EE) ? (__half*)Cv : (__half*)C2v;
        const int coff = (bn < EE) ? 0 : EE;
#pragma unroll
        for (int mf = 0; mf < 4; mf++) {
#pragma unroll
            for (int nf = 0; nf < 4; nf++) {
                const int col = ecol + nf * 8;
                const float bx = bias[col], by = bias[col + 1];
                __half* H0 = Hb + (size_t)(erow + mf * 16) * EE + (col - coff);
                __half* H1 = H0 + (size_t)8 * EE;
                *(__half2*)H0 = __floats2half2_rn(acc[mf][nf][0] + bx,
                                                  acc[mf][nf][1] + by);
                *(__half2*)H1 = __floats2half2_rn(acc[mf][nf][2] + bx,
                                                  acc[mf][nf][3] + by);
            }
        }
    } else {
        float* C = (float*)Cv;
#pragma unroll
        for (int mf = 0; mf < 4; mf++) {
#pragma unroll
            for (int nf = 0; nf < 4; nf++) {
                const int col = ecol + nf * 8;
                const float bx = bias[col], by = bias[col + 1];
                float* C0 = C + (size_t)(erow + mf * 16) * N + col;
                float* C1 = C0 + (size_t)8 * N;
                *(float2*)C0 = make_float2(acc[mf][nf][0] + bx,
                                           acc[mf][nf][1] + by);
                *(float2*)C1 = make_float2(acc[mf][nf][2] + bx,
                                           acc[mf][nf][3] + by);
            }
        }
    }
}

// ============================================================
// Cast x (fp32 [M,DM]) -> fp16 [M,DM] (contiguous)
// ============================================================
__global__ void cast_x_kernel(const float* __restrict__ x,
                              __half* __restrict__ xs)
{
    const int idx = blockIdx.x * 256 + threadIdx.x;  // over M_TOTAL*DM/4
    const float4 v = ((const float4*)x)[idx];
    __half2* o = (__half2*)xs + idx * 2;
    o[0] = __floats2half2_rn(v.x, v.y);
    o[1] = __floats2half2_rn(v.z, v.w);
}

// ============================================================
// Transpose weights: W [K, N] fp32 -> Wt [N, K] fp16
// ============================================================
__global__ __launch_bounds__(256) void wtrans_kernel(
    const float* __restrict__ W, __half* __restrict__ Wt, int K, int N)
{
    __shared__ float t[32][33];
    const int k0 = blockIdx.y * 32;
    const int n0 = blockIdx.x * 32;
    const int tx = threadIdx.x & 31;
    const int ty = threadIdx.x >> 5;  // 0..7

    for (int i = ty; i < 32; i += 8)
        t[i][tx] = W[(size_t)(k0 + i) * N + n0 + tx];
    __syncthreads();

    for (int i = ty; i < 32; i += 8)
        Wt[(size_t)(n0 + i) * K + k0 + tx] = __float2half(t[tx][i]);
}

// ============================================================
// Causal depthwise conv1d, k=4 — fp16 in/out, fp32 math.
// Tiled 32 rows x 512 cols, register rolling window.
// ============================================================
#define CBM 32
#define CBE 512

__global__ __launch_bounds__(256) void conv_kernel(
    const float* __restrict__ cw, const float* __restrict__ cb,
    const __half* __restrict__ xp, __half* __restrict__ xconv)
{
    const int t = threadIdx.x;
    const int c4 = t & 127;              // 4-col group within e-tile
    const int rg = t >> 7;               // row group 0/1 (16 rows each)
    const int e0 = blockIdx.x * CBE + c4 * 4;
    const int m0 = blockIdx.y * CBM + rg * 16;
    const int l0 = m0 & (LSEQ - 1);

    // per-e weights: w[tap][j] for e0+j
    float w[4][4];
#pragma unroll
    for (int j = 0; j < 4; j++) {
        const float4 we = *(const float4*)(cw + (size_t)(e0 + j) * 4);
        w[0][j] = we.x; w[1][j] = we.y; w[2][j] = we.z; w[3][j] = we.w;
    }
    const float4 bias4 = *(const float4*)(cb + e0);

    const __half* xrow = xp + (size_t)m0 * EE + e0;
    __half* orow = xconv + (size_t)m0 * EE + e0;

    float4 xm3, xm2, xm1;
    if (l0 == 0) {
        xm3 = xm2 = xm1 = make_float4(0.f, 0.f, 0.f, 0.f);
    } else {    // l0 >= 16 here, so all three prev rows are in-batch
        xm3 = ld4h(xrow - (size_t)3 * EE);
        xm2 = ld4h(xrow - (size_t)2 * EE);
        xm1 = ld4h(xrow - (size_t)1 * EE);
    }

#pragma unroll
    for (int r = 0; r < 16; r++) {
        const float4 cur = ld4h(xrow + (size_t)r * EE);
        float4 o;
        o.x = bias4.x + w[0][0]*xm3.x + w[1][0]*xm2.x + w[2][0]*xm1.x + w[3][0]*cur.x;
        o.y = bias4.y + w[0][1]*xm3.y + w[1][1]*xm2.y + w[2][1]*xm1.y + w[3][1]*cur.y;
        o.z = bias4.z + w[0][2]*xm3.z + w[1][2]*xm2.z + w[2][2]*xm1.z + w[3][2]*cur.z;
        o.w = bias4.w + w[0][3]*xm3.w + w[1][3]*xm2.w + w[2][3]*xm1.w + w[3][3]*cur.w;
        st4h(orow + (size_t)r * EE, o);
        xm3 = xm2; xm2 = xm1; xm1 = cur;
    }
}

// ============================================================
// u[m,s] = xconv[m,:] . A[:,s]   (fp16 xconv, fp32 math)
// ============================================================
__global__ void u_kernel(const float* __restrict__ Amat, float* __restrict__ u)
{
    const int m = blockIdx.x * 64 + (threadIdx.x >> 2);
    const int sg = (threadIdx.x & 3) * 4;
    const __half* xr = g_xconv + (size_t)m * EE;

    float4 acc = make_float4(0.f, 0.f, 0.f, 0.f);
#pragma unroll 4
    for (int e = 0; e < EE; e += 4) {
        float4 xv = ld4h(xr + e);
        float4 a0 = *(const float4*)(Amat + (e + 0) * DSTATE + sg);
        float4 a1 = *(const float4*)(Amat + (e + 1) * DSTATE + sg);
        float4 a2 = *(const float4*)(Amat + (e + 2) * DSTATE + sg);
        float4 a3 = *(const float4*)(Amat + (e + 3) * DSTATE + sg);
        acc.x += xv.x * a0.x + xv.y * a1.x + xv.z * a2.x + xv.w * a3.x;
        acc.y += xv.x * a0.y + xv.y * a1.y + xv.z * a2.y + xv.w * a3.y;
        acc.z += xv.x * a0.z + xv.y * a1.z + xv.z * a2.z + xv.w * a3.z;
        acc.w += xv.x * a0.w + xv.y * a1.w + xv.z * a2.w + xv.w * a3.w;
    }
    *(float4*)(u + (size_t)m * DSTATE + sg) = acc;
}

// ============================================================
// Sequential scan h_t = tanh(u_t + h_{t-1}), hardware tanh.approx,
// 16-deep load prefetch. 64 independent chains.
// ============================================================
__global__ void scan_kernel(const float* __restrict__ u, float* __restrict__ h)
{
    const int b = threadIdx.x >> 4;
    const int s = threadIdx.x & 15;
    const float* up = u + (size_t)b * LSEQ * DSTATE + s;
    float* hp = h + (size_t)b * LSEQ * DSTATE + s;

    float buf[16], nxt[16];
#pragma unroll
    for (int i = 0; i < 16; i++) buf[i] = __ldg(up + (size_t)i * DSTATE);

    float hv = 0.f;
    for (int l0 = 0; l0 < LSEQ; l0 += 16) {
        if (l0 + 16 < LSEQ) {
#pragma unroll
            for (int i = 0; i < 16; i++)
                nxt[i] = __ldg(up + (size_t)(l0 + 16 + i) * DSTATE);
        }
#pragma unroll
        for (int i = 0; i < 16; i++) {
            hv += buf[i];
            asm("tanh.approx.f32 %0, %0;" : "+f"(hv));
            hp[(size_t)(l0 + i) * DSTATE] = hv;
        }
#pragma unroll
        for (int i = 0; i < 16; i++) buf[i] = nxt[i];
    }
}

// ============================================================
// gated = sigmoid(z) * (h @ C^T + Dp * xconv) -> fp16 [M, EE]
// (fp16 z and xconv inputs, fp32 math)
// ============================================================
__global__ __launch_bounds__(256) void gated_kernel(
    const float* __restrict__ Cmat, const float* __restrict__ Dp,
    const float* __restrict__ h, __half* __restrict__ gs)
{
    __shared__ float C_sh[256][17];
    __shared__ float h_sh[16][16];

    const int tid = threadIdx.x;
    const int e0 = blockIdx.x * 256;
    const int m0 = blockIdx.y * 16;

    {
        const float* crow = Cmat + (size_t)(e0 + tid) * DSTATE;
#pragma unroll
        for (int i = 0; i < DSTATE; i++) C_sh[tid][i] = crow[i];
    }
    ((float*)h_sh)[tid] = h[(size_t)m0 * DSTATE + tid];
    __syncthreads();

    const int e = e0 + tid;
    float creg[DSTATE];
#pragma unroll
    for (int i = 0; i < DSTATE; i++) creg[i] = C_sh[tid][i];
    const float dpe = Dp[e];

#pragma unroll
    for (int mi = 0; mi < 16; mi++) {
        const int m = m0 + mi;
        float dot = 0.f;
#pragma unroll
        for (int i = 0; i < DSTATE; i++) dot = fmaf(h_sh[mi][i], creg[i], dot);
        const float z = __half2float(g_zp[(size_t)m * EE + e]);
        const float xcv = __half2float(g_xconv[(size_t)m * EE + e]);
        const float sig = 1.f / (1.f + __expf(-z));
        gs[(size_t)m * EE + e] = __float2half(sig * (dot + dpe * xcv));
    }
}

// ============================================================
extern "C" void kernel_launch(void* const* d_in, const int* in_sizes, int n_in,
                              void* d_out, int out_size)
{
    const float* x      = (const float*)d_in[0];
    const float* W_in   = (const float*)d_in[1];
    const float* b_in   = (const float*)d_in[2];
    const float* conv_w = (const float*)d_in[3];
    const float* conv_b = (const float*)d_in[4];
    const float* Amat   = (const float*)d_in[5];
    const float* Cmat   = (const float*)d_in[6];
    const float* Dp     = (const float*)d_in[7];
    const float* W_out  = (const float*)d_in[8];
    const float* b_out  = (const float*)d_in[9];
    float* out = (float*)d_out;

    __half* xp    = nullptr; cudaGetSymbolAddress((void**)&xp,    g_xp);
    __half* zp    = nullptr; cudaGetSymbolAddress((void**)&zp,    g_zp);
    __half* xconv = nullptr; cudaGetSymbolAddress((void**)&xconv, g_xconv);
    float* u      = nullptr; cudaGetSymbolAddress((void**)&u,     g_u);
    float* h      = nullptr; cudaGetSymbolAddress((void**)&h,     g_h);
    __half* xs = nullptr; cudaGetSymbolAddress((void**)&xs, g_xs);
    __half* w1 = nullptr; cudaGetSymbolAddress((void**)&w1, g_w1);
    __half* gs = nullptr; cudaGetSymbolAddress((void**)&gs, g_gs);
    __half* w2 = nullptr; cudaGetSymbolAddress((void**)&w2, g_w2);

    cudaFuncSetAttribute(mm_gemm, cudaFuncAttributeMaxDynamicSharedMemorySize,
                         MM_SMEM_BYTES);

    // 0) casts / transposes
    cast_x_kernel<<<(M_TOTAL * DM / 4) / 256, 256>>>(x, xs);
    {
        dim3 g1(N1 / 32, DM / 32);
        wtrans_kernel<<<g1, 256>>>(W_in, w1, DM, N1);
        dim3 g2(DM / 32, EE / 32);
        wtrans_kernel<<<g2, 256>>>(W_out, w2, EE, DM);
    }

    // 1) [x_proj | z] = x @ W_in + b_in  (fp16 GEMM, fp16 split outputs)
    {
        dim3 grid(N1 / TBN, M_TOTAL / TBM);
        mm_gemm<<<grid, 256, MM_SMEM_BYTES>>>(xs, w1, b_in, xp, zp,
                                              N1, KP1, 1);
    }

    // 2) causal depthwise conv (fp16 in/out, fp32 math)
    {
        dim3 grid(EE / CBE, M_TOTAL / CBM);
        conv_kernel<<<grid, 256>>>(conv_w, conv_b, xp, xconv);
    }

    // 3) u = xconv @ A
    u_kernel<<<M_TOTAL / 64, 256>>>(Amat, u);

    // 4) sequential tanh scan
    scan_kernel<<<1, BATCH * DSTATE>>>(u, h);

    // 5) gated (fp16 inputs, writes fp16)
    {
        dim3 grid(EE / 256, M_TOTAL / 16);
        gated_kernel<<<grid, 256>>>(Cmat, Dp, h, gs);
    }

    // 6) out = gated @ W_out + b_out  (fp16, K = 2048, fp32 out)
    {
        dim3 grid(DM / TBN, M_TOTAL / TBM);
        mm_gemm<<<grid, 256, MM_SMEM_BYTES>>>(gs, w2, b_out, out, nullptr,
                                              DM, KP2, 0);
    }
}

// round 16
// speedup vs baseline: 1.0143x; 1.0143x over previous
#include <cuda_runtime.h>
#include <cuda_fp16.h>
#include <cstdint>
#include <math.h>

#define BATCH   4
#define LSEQ    4096
#define M_TOTAL (BATCH * LSEQ)   // 16384
#define DM      1024
#define EE      2048             // E
#define N1      (2 * EE)         // 4096
#define DSTATE  16
#define DCONV   4

#define KP1 DM                   // 1024  fp16 single-pass GEMM1
#define KP2 EE                   // 2048  fp16 single-pass GEMM2

// -------- scratch (device globals: allocation-free rule) --------
__device__ float  g_xp[M_TOTAL * (size_t)EE];     // 128 MB  x_proj
__device__ float  g_sz[M_TOTAL * (size_t)EE];     // 128 MB  sigmoid(z)
__device__ float  g_xconv[M_TOTAL * (size_t)EE];  // 128 MB
__device__ float  g_u[M_TOTAL * DSTATE];          // 1 MB
__device__ float  g_h[M_TOTAL * DSTATE];          // 1 MB
__device__ __half g_xs[M_TOTAL * (size_t)KP1];    // 32 MB  A for GEMM1
__device__ __half g_w1[(size_t)N1 * KP1];         // 8 MB   B for GEMM1
__device__ __half g_gs[M_TOTAL * (size_t)KP2];    // 64 MB  A for GEMM2
__device__ __half g_w2[(size_t)DM * KP2];         // 4 MB   B for GEMM2

// ============================================================
// helpers
// ============================================================
__device__ __forceinline__ uint32_t smem_u32(const void* p) {
    uint32_t a;
    asm("{ .reg .u64 t; cvta.to.shared.u64 t, %1; cvt.u32.u64 %0, t; }"
        : "=r"(a) : "l"(p));
    return a;
}

#define CP_ASYNC_16(dst_u32, src_ptr) \
    asm volatile("cp.async.cg.shared.global [%0], [%1], 16;" \
                 :: "r"(dst_u32), "l"(src_ptr) : "memory")
#define CP_ASYNC_COMMIT() asm volatile("cp.async.commit_group;" ::: "memory")
#define CP_ASYNC_WAIT1()  asm volatile("cp.async.wait_group 1;" ::: "memory")

__device__ __forceinline__ void ldm_x4(uint32_t& r0, uint32_t& r1,
                                       uint32_t& r2, uint32_t& r3, uint32_t addr) {
    asm volatile("ldmatrix.sync.aligned.m8n8.x4.shared.b16 {%0,%1,%2,%3}, [%4];"
                 : "=r"(r0), "=r"(r1), "=r"(r2), "=r"(r3) : "r"(addr));
}
__device__ __forceinline__ void mma_f16(float* d, const uint32_t* a,
                                        const uint32_t* b) {
    asm volatile(
        "mma.sync.aligned.m16n8k16.row.col.f32.f16.f16.f32 "
        "{%0,%1,%2,%3}, {%4,%5,%6,%7}, {%8,%9}, {%0,%1,%2,%3};"
        : "+f"(d[0]), "+f"(d[1]), "+f"(d[2]), "+f"(d[3])
        : "r"(a[0]), "r"(a[1]), "r"(a[2]), "r"(a[3]), "r"(b[0]), "r"(b[1]));
}

// ============================================================
// fp16 mma.sync GEMM: C = A[M,KP] @ B[N,KP]^T + bias[N]
// 128x128 CTA tile, BK=64, 8 warps (warp tile 64m x 32n),
// 3-stage cp.async pipeline, XOR-swizzled 128B rows.
// mode 0: fp32 C [M,N] (stride N)
// mode 1: cols <  EE -> C  (x_proj, raw, stride EE)
//         cols >= EE -> C2 (SIGMOID applied in epilogue, stride EE)
// ============================================================
#define TBM 128
#define TBN 128
#define TBK 64
#define ROWB 128                             // bytes per smem row (64 fp16)
#define STAGE_A_BYTES (TBM * ROWB)           // 16384
#define STAGE_BYTES   (2 * STAGE_A_BYTES)    // 32768 (A then B)
#define NSTAGE 3
#define MM_SMEM_BYTES (NSTAGE * STAGE_BYTES) // 98304

__device__ __forceinline__ uint32_t swz(int row, int g) {
    return (uint32_t)(row * ROWB) + (uint32_t)((g ^ (row & 7)) << 4);
}

__global__ __launch_bounds__(256, 2) void mm_gemm(
    const __half* __restrict__ A,
    const __half* __restrict__ B,
    const float* __restrict__ bias,
    float* __restrict__ C,
    float* __restrict__ C2,
    int N, int KP, int mode)
{
    extern __shared__ char dynsmem[];
    const uint32_t sbase = smem_u32(dynsmem);

    const int tid = threadIdx.x;
    const int wid = tid >> 5;
    const int lane = tid & 31;
    const int bm = blockIdx.y * TBM;
    const int bn = blockIdx.x * TBN;

    const int wm = (wid & 1) * 64;   // warp m-offset in tile
    const int wn = (wid >> 1) * 32;  // warp n-offset in tile

    // ---- global->shared mapping
    const int grow = tid >> 1;             // 0..127
    const int gg0 = (tid & 1) * 4;         // 0 or 4
    const __half* Agl = A + (size_t)(bm + grow) * KP + gg0 * 8;
    const __half* Bgl = B + (size_t)(bn + grow) * KP + gg0 * 8;
    uint32_t gdst[4];
#pragma unroll
    for (int i = 0; i < 4; i++) gdst[i] = swz(grow, gg0 + i);

    uint32_t sA[NSTAGE], sB[NSTAGE];
#pragma unroll
    for (int s = 0; s < NSTAGE; s++) {
        sA[s] = sbase + s * STAGE_BYTES;
        sB[s] = sA[s] + STAGE_A_BYTES;
    }

    float acc[4][4][4];
#pragma unroll
    for (int i = 0; i < 4; i++)
#pragma unroll
        for (int j = 0; j < 4; j++)
#pragma unroll
            for (int k = 0; k < 4; k++) acc[i][j][k] = 0.f;

    // ---- ldmatrix per-thread bases
    const int arow = wm + (lane & 15);
    const int axor = arow & 7;
    const int agl = lane >> 4;
    const int brow = wn + (lane & 7) + ((lane >> 4) << 3);
    const int bxor = brow & 7;
    const int bgl = (lane >> 3) & 1;

    const int nchunk = KP / TBK;

    // prologue
#pragma unroll
    for (int s = 0; s < NSTAGE - 1; s++) {
        const size_t koff = (size_t)s * TBK;
#pragma unroll
        for (int i = 0; i < 4; i++) {
            CP_ASYNC_16(sA[s] + gdst[i], Agl + koff + i * 8);
            CP_ASYNC_16(sB[s] + gdst[i], Bgl + koff + i * 8);
        }
        CP_ASYNC_COMMIT();
    }

    int buf = 0, nbuf = NSTAGE - 1;
    for (int c = 0; c < nchunk; c++) {
        CP_ASYNC_WAIT1();
        __syncthreads();

        if (c + NSTAGE - 1 < nchunk) {
            const size_t koff = (size_t)(c + NSTAGE - 1) * TBK;
#pragma unroll
            for (int i = 0; i < 4; i++) {
                CP_ASYNC_16(sA[nbuf] + gdst[i], Agl + koff + i * 8);
                CP_ASYNC_16(sB[nbuf] + gdst[i], Bgl + koff + i * 8);
            }
        }
        CP_ASYNC_COMMIT();

#pragma unroll
        for (int ks = 0; ks < 4; ks++) {
            uint32_t af[4][4], bfr[4][2];
#pragma unroll
            for (int mf = 0; mf < 4; mf++) {
                const int row = arow + mf * 16;
                const uint32_t addr =
                    sA[buf] + row * ROWB + (((ks * 2 + agl) ^ axor) << 4);
                ldm_x4(af[mf][0], af[mf][1], af[mf][2], af[mf][3], addr);
            }
#pragma unroll
            for (int nfp = 0; nfp < 2; nfp++) {
                const int row = brow + nfp * 16;
                const uint32_t addr =
                    sB[buf] + row * ROWB + (((ks * 2 + bgl) ^ bxor) << 4);
                ldm_x4(bfr[nfp * 2][0], bfr[nfp * 2][1],
                       bfr[nfp * 2 + 1][0], bfr[nfp * 2 + 1][1], addr);
            }
#pragma unroll
            for (int mf = 0; mf < 4; mf++)
#pragma unroll
                for (int nf = 0; nf < 4; nf++)
                    mma_f16(acc[mf][nf], af[mf], bfr[nf]);
        }

        buf = (buf + 1 == NSTAGE) ? 0 : buf + 1;
        nbuf = (nbuf + 1 == NSTAGE) ? 0 : nbuf + 1;
    }

    // epilogue
    const int erow = bm + wm + (lane >> 2);
    const int ecol = bn + wn + (lane & 3) * 2;

    if (mode == 1) {
        const bool zhalf = (bn >= EE);          // uniform per block
        float* Cb = zhalf ? C2 : C;
        const int coff = zhalf ? EE : 0;
#pragma unroll
        for (int mf = 0; mf < 4; mf++) {
#pragma unroll
            for (int nf = 0; nf < 4; nf++) {
                const int col = ecol + nf * 8;
                const float bx = bias[col], by = bias[col + 1];
                float v0 = acc[mf][nf][0] + bx;
                float v1 = acc[mf][nf][1] + by;
                float v2 = acc[mf][nf][2] + bx;
                float v3 = acc[mf][nf][3] + by;
                if (zhalf) {                     // store sigmoid(z)
                    v0 = 1.f / (1.f + __expf(-v0));
                    v1 = 1.f / (1.f + __expf(-v1));
                    v2 = 1.f / (1.f + __expf(-v2));
                    v3 = 1.f / (1.f + __expf(-v3));
                }
                float* C0 = Cb + (size_t)(erow + mf * 16) * EE + (col - coff);
                float* C1 = C0 + (size_t)8 * EE;
                *(float2*)C0 = make_float2(v0, v1);
                *(float2*)C1 = make_float2(v2, v3);
            }
        }
    } else {
#pragma unroll
        for (int mf = 0; mf < 4; mf++) {
#pragma unroll
            for (int nf = 0; nf < 4; nf++) {
                const int col = ecol + nf * 8;
                const float bx = bias[col], by = bias[col + 1];
                float* C0 = C + (size_t)(erow + mf * 16) * N + col;
                float* C1 = C0 + (size_t)8 * N;
                *(float2*)C0 = make_float2(acc[mf][nf][0] + bx,
                                           acc[mf][nf][1] + by);
                *(float2*)C1 = make_float2(acc[mf][nf][2] + bx,
                                           acc[mf][nf][3] + by);
            }
        }
    }
}

// ============================================================
// Prep: ONE launch doing x->fp16 cast + both weight transposes.
// blocks [0, 16384)          : cast x
// blocks [16384, 16384+4096) : W_in  [1024,4096] -> w1 [4096,1024] fp16
// blocks [20480, 20480+2048) : W_out [2048,1024] -> w2 [1024,2048] fp16
// ============================================================
__global__ __launch_bounds__(256) void prep_kernel(
    const float* __restrict__ x, __half* __restrict__ xs,
    const float* __restrict__ W_in, __half* __restrict__ w1,
    const float* __restrict__ W_out, __half* __restrict__ w2)
{
    __shared__ float t[32][33];
    const int b = blockIdx.x;
    const int tid = threadIdx.x;

    if (b < 16384) {                     // cast x (float4 per thread)
        const int idx = b * 256 + tid;
        const float4 v = ((const float4*)x)[idx];
        __half2* o = (__half2*)xs + idx * 2;
        o[0] = __floats2half2_rn(v.x, v.y);
        o[1] = __floats2half2_rn(v.z, v.w);
        return;
    }

    const float* W;
    __half* Wt;
    int K, N, bx, by;
    if (b < 16384 + 4096) {
        const int bb = b - 16384;
        W = W_in; Wt = w1; K = DM; N = N1;
        bx = bb & 127; by = bb >> 7;     // N/32 = 128
    } else {
        const int bb = b - 20480;
        W = W_out; Wt = w2; K = EE; N = DM;
        bx = bb & 31; by = bb >> 5;      // N/32 = 32
    }
    const int k0 = by * 32;
    const int n0 = bx * 32;
    const int tx = tid & 31;
    const int ty = tid >> 5;             // 0..7

    for (int i = ty; i < 32; i += 8)
        t[i][tx] = W[(size_t)(k0 + i) * N + n0 + tx];
    __syncthreads();

    for (int i = ty; i < 32; i += 8)
        Wt[(size_t)(n0 + i) * K + k0 + tx] = __float2half(t[tx][i]);
}

// ============================================================
// Causal depthwise conv1d, k=4 — tiled 32 rows x 512 cols,
// register rolling window (~1.09x read amplification). fp32.
// ============================================================
#define CBM 32
#define CBE 512

__global__ __launch_bounds__(256) void conv_kernel(
    const float* __restrict__ cw, const float* __restrict__ cb,
    const float* __restrict__ xp, float* __restrict__ xconv)
{
    const int t = threadIdx.x;
    const int c4 = t & 127;              // float4 column within e-tile
    const int rg = t >> 7;               // row group 0/1 (16 rows each)
    const int e0 = blockIdx.x * CBE + c4 * 4;
    const int m0 = blockIdx.y * CBM + rg * 16;
    const int l0 = m0 & (LSEQ - 1);

    float w[4][4];
#pragma unroll
    for (int j = 0; j < 4; j++) {
        const float4 we = *(const float4*)(cw + (size_t)(e0 + j) * 4);
        w[0][j] = we.x; w[1][j] = we.y; w[2][j] = we.z; w[3][j] = we.w;
    }
    const float4 bias4 = *(const float4*)(cb + e0);

    const float* xrow = xp + (size_t)m0 * EE + e0;
    float* orow = xconv + (size_t)m0 * EE + e0;

    float4 xm3, xm2, xm1;
    if (l0 == 0) {
        xm3 = xm2 = xm1 = make_float4(0.f, 0.f, 0.f, 0.f);
    } else {    // l0 >= 16 here, so all three prev rows are in-batch
        xm3 = *(const float4*)(xrow - (size_t)3 * EE);
        xm2 = *(const float4*)(xrow - (size_t)2 * EE);
        xm1 = *(const float4*)(xrow - (size_t)1 * EE);
    }

#pragma unroll
    for (int r = 0; r < 16; r++) {
        const float4 cur = *(const float4*)(xrow + (size_t)r * EE);
        float4 o;
        o.x = bias4.x + w[0][0]*xm3.x + w[1][0]*xm2.x + w[2][0]*xm1.x + w[3][0]*cur.x;
        o.y = bias4.y + w[0][1]*xm3.y + w[1][1]*xm2.y + w[2][1]*xm1.y + w[3][1]*cur.y;
        o.z = bias4.z + w[0][2]*xm3.z + w[1][2]*xm2.z + w[2][2]*xm1.z + w[3][2]*cur.z;
        o.w = bias4.w + w[0][3]*xm3.w + w[1][3]*xm2.w + w[2][3]*xm1.w + w[3][3]*cur.w;
        *(float4*)(orow + (size_t)r * EE) = o;
        xm3 = xm2; xm2 = xm1; xm1 = cur;
    }
}

// ============================================================
// u[m,s] = xconv[m,:] . A[:,s]
// ============================================================
__global__ void u_kernel(const float* __restrict__ Amat, float* __restrict__ u)
{
    const int m = blockIdx.x * 64 + (threadIdx.x >> 2);
    const int sg = (threadIdx.x & 3) * 4;
    const float* xr = g_xconv + (size_t)m * EE;

    float4 acc = make_float4(0.f, 0.f, 0.f, 0.f);
#pragma unroll 4
    for (int e = 0; e < EE; e += 4) {
        float4 xv = *(const float4*)(xr + e);
        float4 a0 = *(const float4*)(Amat + (e + 0) * DSTATE + sg);
        float4 a1 = *(const float4*)(Amat + (e + 1) * DSTATE + sg);
        float4 a2 = *(const float4*)(Amat + (e + 2) * DSTATE + sg);
        float4 a3 = *(const float4*)(Amat + (e + 3) * DSTATE + sg);
        acc.x += xv.x * a0.x + xv.y * a1.x + xv.z * a2.x + xv.w * a3.x;
        acc.y += xv.x * a0.y + xv.y * a1.y + xv.z * a2.y + xv.w * a3.y;
        acc.z += xv.x * a0.z + xv.y * a1.z + xv.z * a2.z + xv.w * a3.z;
        acc.w += xv.x * a0.w + xv.y * a1.w + xv.z * a2.w + xv.w * a3.w;
    }
    *(float4*)(u + (size_t)m * DSTATE + sg) = acc;
}

// ============================================================
// Sequential scan h_t = tanh(u_t + h_{t-1}), hardware tanh.approx,
// 16-deep load prefetch. 64 independent chains.
// ============================================================
__global__ void scan_kernel(const float* __restrict__ u, float* __restrict__ h)
{
    const int b = threadIdx.x >> 4;
    const int s = threadIdx.x & 15;
    const float* up = u + (size_t)b * LSEQ * DSTATE + s;
    float* hp = h + (size_t)b * LSEQ * DSTATE + s;

    float buf[16], nxt[16];
#pragma unroll
    for (int i = 0; i < 16; i++) buf[i] = __ldg(up + (size_t)i * DSTATE);

    float hv = 0.f;
    for (int l0 = 0; l0 < LSEQ; l0 += 16) {
        if (l0 + 16 < LSEQ) {
#pragma unroll
            for (int i = 0; i < 16; i++)
                nxt[i] = __ldg(up + (size_t)(l0 + 16 + i) * DSTATE);
        }
#pragma unroll
        for (int i = 0; i < 16; i++) {
            hv += buf[i];
            asm("tanh.approx.f32 %0, %0;" : "+f"(hv));
            hp[(size_t)(l0 + i) * DSTATE] = hv;
        }
#pragma unroll
        for (int i = 0; i < 16; i++) buf[i] = nxt[i];
    }
}

// ============================================================
// gated = sig * (h @ C^T + Dp * xconv) -> fp16 [M, EE]
// (sig = precomputed sigmoid(z) from GEMM1 epilogue; pure FMA here)
// ============================================================
__global__ __launch_bounds__(256) void gated_kernel(
    const float* __restrict__ Cmat, const float* __restrict__ Dp,
    const float* __restrict__ h, __half* __restrict__ gs)
{
    __shared__ float C_sh[256][17];
    __shared__ float h_sh[16][16];

    const int tid = threadIdx.x;
    const int e0 = blockIdx.x * 256;
    const int m0 = blockIdx.y * 16;

    {
        const float* crow = Cmat + (size_t)(e0 + tid) * DSTATE;
#pragma unroll
        for (int i = 0; i < DSTATE; i++) C_sh[tid][i] = crow[i];
    }
    ((float*)h_sh)[tid] = h[(size_t)m0 * DSTATE + tid];
    __syncthreads();

    const int e = e0 + tid;
    float creg[DSTATE];
#pragma unroll
    for (int i = 0; i < DSTATE; i++) creg[i] = C_sh[tid][i];
    const float dpe = Dp[e];

#pragma unroll
    for (int mi = 0; mi < 16; mi++) {
        const int m = m0 + mi;
        float dot = 0.f;
#pragma unroll
        for (int i = 0; i < DSTATE; i++) dot = fmaf(h_sh[mi][i], creg[i], dot);
        const float sig = g_sz[(size_t)m * EE + e];
        const float xcv = g_xconv[(size_t)m * EE + e];
        gs[(size_t)m * EE + e] = __float2half(sig * (dot + dpe * xcv));
    }
}

// ============================================================
extern "C" void kernel_launch(void* const* d_in, const int* in_sizes, int n_in,
                              void* d_out, int out_size)
{
    const float* x      = (const float*)d_in[0];
    const float* W_in   = (const float*)d_in[1];
    const float* b_in   = (const float*)d_in[2];
    const float* conv_w = (const float*)d_in[3];
    const float* conv_b = (const float*)d_in[4];
    const float* Amat   = (const float*)d_in[5];
    const float* Cmat   = (const float*)d_in[6];
    const float* Dp     = (const float*)d_in[7];
    const float* W_out  = (const float*)d_in[8];
    const float* b_out  = (const float*)d_in[9];
    float* out = (float*)d_out;

    float* xp    = nullptr; cudaGetSymbolAddress((void**)&xp,    g_xp);
    float* sz    = nullptr; cudaGetSymbolAddress((void**)&sz,    g_sz);
    float* xconv = nullptr; cudaGetSymbolAddress((void**)&xconv, g_xconv);
    float* u     = nullptr; cudaGetSymbolAddress((void**)&u,     g_u);
    float* h     = nullptr; cudaGetSymbolAddress((void**)&h,     g_h);
    __half* xs = nullptr; cudaGetSymbolAddress((void**)&xs, g_xs);
    __half* w1 = nullptr; cudaGetSymbolAddress((void**)&w1, g_w1);
    __half* gs = nullptr; cudaGetSymbolAddress((void**)&gs, g_gs);
    __half* w2 = nullptr; cudaGetSymbolAddress((void**)&w2, g_w2);

    cudaFuncSetAttribute(mm_gemm, cudaFuncAttributeMaxDynamicSharedMemorySize,
                         MM_SMEM_BYTES);

    // 0) prep: cast x + transpose both weights (single launch)
    prep_kernel<<<16384 + 4096 + 2048, 256>>>(x, xs, W_in, w1, W_out, w2);

    // 1) [x_proj | sigmoid(z)] = x @ W_in + b_in  (split epilogue)
    {
        dim3 grid(N1 / TBN, M_TOTAL / TBM);
        mm_gemm<<<grid, 256, MM_SMEM_BYTES>>>(xs, w1, b_in, xp, sz,
                                              N1, KP1, 1);
    }

    // 2) causal depthwise conv (tiled, rolling window)
    {
        dim3 grid(EE / CBE, M_TOTAL / CBM);
        conv_kernel<<<grid, 256>>>(conv_w, conv_b, xp, xconv);
    }

    // 3) u = xconv @ A
    u_kernel<<<M_TOTAL / 64, 256>>>(Amat, u);

    // 4) sequential tanh scan
    scan_kernel<<<1, BATCH * DSTATE>>>(u, h);

    // 5) gated (pure FMA; sigmoid precomputed)
    {
        dim3 grid(EE / 256, M_TOTAL / 16);
        gated_kernel<<<grid, 256>>>(Cmat, Dp, h, gs);
    }

    // 6) out = gated @ W_out + b_out  (fp16, K = 2048, fp32 out)
    {
        dim3 grid(DM / TBN, M_TOTAL / TBM);
        mm_gemm<<<grid, 256, MM_SMEM_BYTES>>>(gs, w2, b_out, out, nullptr,
                                              DM, KP2, 0);
    }
}

// round 17
// speedup vs baseline: 1.1708x; 1.1543x over previous
#include <cuda_runtime.h>
#include <cuda_fp16.h>
#include <cstdint>
#include <math.h>

#define BATCH   4
#define LSEQ    4096
#define M_TOTAL (BATCH * LSEQ)   // 16384
#define DM      1024
#define EE      2048             // E
#define N1      (2 * EE)         // 4096
#define DSTATE  16
#define DCONV   4

#define KP1 DM                   // 1024  fp16 single-pass GEMM1
#define KP2 EE                   // 2048  fp16 single-pass GEMM2

// -------- scratch (device globals: allocation-free rule) --------
__device__ float  g_xp[M_TOTAL * (size_t)EE];     // 128 MB  x_proj
__device__ float  g_zp[M_TOTAL * (size_t)EE];     // 128 MB  z
__device__ float  g_xconv[M_TOTAL * (size_t)EE];  // 128 MB  (fp32, for gated)
__device__ __half g_xch[M_TOTAL * (size_t)EE];    // 64 MB   xconv fp16 (for u)
__device__ __half g_Ah[DSTATE * (size_t)EE];      // 64 KB   A^T fp16 [16,2048]
__device__ float  g_u[M_TOTAL * DSTATE];          // 1 MB
__device__ float  g_h[M_TOTAL * DSTATE];          // 1 MB
__device__ __half g_xs[M_TOTAL * (size_t)KP1];    // 32 MB  A for GEMM1
__device__ __half g_w1[(size_t)N1 * KP1];         // 8 MB   B for GEMM1
__device__ __half g_gs[M_TOTAL * (size_t)KP2];    // 64 MB  A for GEMM2
__device__ __half g_w2[(size_t)DM * KP2];         // 4 MB   B for GEMM2

// ============================================================
// helpers
// ============================================================
__device__ __forceinline__ uint32_t smem_u32(const void* p) {
    uint32_t a;
    asm("{ .reg .u64 t; cvta.to.shared.u64 t, %1; cvt.u32.u64 %0, t; }"
        : "=r"(a) : "l"(p));
    return a;
}

#define CP_ASYNC_16(dst_u32, src_ptr) \
    asm volatile("cp.async.cg.shared.global [%0], [%1], 16;" \
                 :: "r"(dst_u32), "l"(src_ptr) : "memory")
#define CP_ASYNC_COMMIT() asm volatile("cp.async.commit_group;" ::: "memory")
#define CP_ASYNC_WAIT1()  asm volatile("cp.async.wait_group 1;" ::: "memory")

__device__ __forceinline__ void ldm_x4(uint32_t& r0, uint32_t& r1,
                                       uint32_t& r2, uint32_t& r3, uint32_t addr) {
    asm volatile("ldmatrix.sync.aligned.m8n8.x4.shared.b16 {%0,%1,%2,%3}, [%4];"
                 : "=r"(r0), "=r"(r1), "=r"(r2), "=r"(r3) : "r"(addr));
}
__device__ __forceinline__ void mma_f16(float* d, const uint32_t* a,
                                        const uint32_t* b) {
    asm volatile(
        "mma.sync.aligned.m16n8k16.row.col.f32.f16.f16.f32 "
        "{%0,%1,%2,%3}, {%4,%5,%6,%7}, {%8,%9}, {%0,%1,%2,%3};"
        : "+f"(d[0]), "+f"(d[1]), "+f"(d[2]), "+f"(d[3])
        : "r"(a[0]), "r"(a[1]), "r"(a[2]), "r"(a[3]), "r"(b[0]), "r"(b[1]));
}

__device__ __forceinline__ void st4h(__half* p, float4 v) {
    uint2 raw;
    *(__half2*)&raw.x = __floats2half2_rn(v.x, v.y);
    *(__half2*)&raw.y = __floats2half2_rn(v.z, v.w);
    *(uint2*)p = raw;
}

// ============================================================
// fp16 mma.sync GEMM: C = A[M,KP] @ B[N,KP]^T + bias[N]
// 128x128 CTA tile, BK=64, 8 warps (warp tile 64m x 32n),
// 3-stage cp.async pipeline, XOR-swizzled 128B rows.
// mode 0: fp32 C [M,N] (stride N)
// mode 1: cols < EE -> C; cols >= EE -> C2 (both fp32, stride EE)
// ============================================================
#define TBM 128
#define TBN 128
#define TBK 64
#define ROWB 128                             // bytes per smem row (64 fp16)
#define STAGE_A_BYTES (TBM * ROWB)           // 16384
#define STAGE_BYTES   (2 * STAGE_A_BYTES)    // 32768 (A then B)
#define NSTAGE 3
#define MM_SMEM_BYTES (NSTAGE * STAGE_BYTES) // 98304

__device__ __forceinline__ uint32_t swz(int row, int g) {
    return (uint32_t)(row * ROWB) + (uint32_t)((g ^ (row & 7)) << 4);
}

__global__ __launch_bounds__(256, 2) void mm_gemm(
    const __half* __restrict__ A,
    const __half* __restrict__ B,
    const float* __restrict__ bias,
    float* __restrict__ C,
    float* __restrict__ C2,
    int N, int KP, int mode)
{
    extern __shared__ char dynsmem[];
    const uint32_t sbase = smem_u32(dynsmem);

    const int tid = threadIdx.x;
    const int wid = tid >> 5;
    const int lane = tid & 31;
    const int bm = blockIdx.y * TBM;
    const int bn = blockIdx.x * TBN;

    const int wm = (wid & 1) * 64;
    const int wn = (wid >> 1) * 32;

    const int grow = tid >> 1;
    const int gg0 = (tid & 1) * 4;
    const __half* Agl = A + (size_t)(bm + grow) * KP + gg0 * 8;
    const __half* Bgl = B + (size_t)(bn + grow) * KP + gg0 * 8;
    uint32_t gdst[4];
#pragma unroll
    for (int i = 0; i < 4; i++) gdst[i] = swz(grow, gg0 + i);

    uint32_t sA[NSTAGE], sB[NSTAGE];
#pragma unroll
    for (int s = 0; s < NSTAGE; s++) {
        sA[s] = sbase + s * STAGE_BYTES;
        sB[s] = sA[s] + STAGE_A_BYTES;
    }

    float acc[4][4][4];
#pragma unroll
    for (int i = 0; i < 4; i++)
#pragma unroll
        for (int j = 0; j < 4; j++)
#pragma unroll
            for (int k = 0; k < 4; k++) acc[i][j][k] = 0.f;

    const int arow = wm + (lane & 15);
    const int axor = arow & 7;
    const int agl = lane >> 4;
    const int brow = wn + (lane & 7) + ((lane >> 4) << 3);
    const int bxor = brow & 7;
    const int bgl = (lane >> 3) & 1;

    const int nchunk = KP / TBK;

#pragma unroll
    for (int s = 0; s < NSTAGE - 1; s++) {
        const size_t koff = (size_t)s * TBK;
#pragma unroll
        for (int i = 0; i < 4; i++) {
            CP_ASYNC_16(sA[s] + gdst[i], Agl + koff + i * 8);
            CP_ASYNC_16(sB[s] + gdst[i], Bgl + koff + i * 8);
        }
        CP_ASYNC_COMMIT();
    }

    int buf = 0, nbuf = NSTAGE - 1;
    for (int c = 0; c < nchunk; c++) {
        CP_ASYNC_WAIT1();
        __syncthreads();

        if (c + NSTAGE - 1 < nchunk) {
            const size_t koff = (size_t)(c + NSTAGE - 1) * TBK;
#pragma unroll
            for (int i = 0; i < 4; i++) {
                CP_ASYNC_16(sA[nbuf] + gdst[i], Agl + koff + i * 8);
                CP_ASYNC_16(sB[nbuf] + gdst[i], Bgl + koff + i * 8);
            }
        }
        CP_ASYNC_COMMIT();

#pragma unroll
        for (int ks = 0; ks < 4; ks++) {
            uint32_t af[4][4], bfr[4][2];
#pragma unroll
            for (int mf = 0; mf < 4; mf++) {
                const int row = arow + mf * 16;
                const uint32_t addr =
                    sA[buf] + row * ROWB + (((ks * 2 + agl) ^ axor) << 4);
                ldm_x4(af[mf][0], af[mf][1], af[mf][2], af[mf][3], addr);
            }
#pragma unroll
            for (int nfp = 0; nfp < 2; nfp++) {
                const int row = brow + nfp * 16;
                const uint32_t addr =
                    sB[buf] + row * ROWB + (((ks * 2 + bgl) ^ bxor) << 4);
                ldm_x4(bfr[nfp * 2][0], bfr[nfp * 2][1],
                       bfr[nfp * 2 + 1][0], bfr[nfp * 2 + 1][1], addr);
            }
#pragma unroll
            for (int mf = 0; mf < 4; mf++)
#pragma unroll
                for (int nf = 0; nf < 4; nf++)
                    mma_f16(acc[mf][nf], af[mf], bfr[nf]);
        }

        buf = (buf + 1 == NSTAGE) ? 0 : buf + 1;
        nbuf = (nbuf + 1 == NSTAGE) ? 0 : nbuf + 1;
    }

    const int erow = bm + wm + (lane >> 2);
    const int ecol = bn + wn + (lane & 3) * 2;

    if (mode == 1) {
        const bool zhalf = (bn >= EE);
        float* Cb = zhalf ? C2 : C;
        const int coff = zhalf ? EE : 0;
#pragma unroll
        for (int mf = 0; mf < 4; mf++) {
#pragma unroll
            for (int nf = 0; nf < 4; nf++) {
                const int col = ecol + nf * 8;
                const float bx = bias[col], by = bias[col + 1];
                float* C0 = Cb + (size_t)(erow + mf * 16) * EE + (col - coff);
                float* C1 = C0 + (size_t)8 * EE;
                *(float2*)C0 = make_float2(acc[mf][nf][0] + bx,
                                           acc[mf][nf][1] + by);
                *(float2*)C1 = make_float2(acc[mf][nf][2] + bx,
                                           acc[mf][nf][3] + by);
            }
        }
    } else {
#pragma unroll
        for (int mf = 0; mf < 4; mf++) {
#pragma unroll
            for (int nf = 0; nf < 4; nf++) {
                const int col = ecol + nf * 8;
                const float bx = bias[col], by = bias[col + 1];
                float* C0 = C + (size_t)(erow + mf * 16) * N + col;
                float* C1 = C0 + (size_t)8 * N;
                *(float2*)C0 = make_float2(acc[mf][nf][0] + bx,
                                           acc[mf][nf][1] + by);
                *(float2*)C1 = make_float2(acc[mf][nf][2] + bx,
                                           acc[mf][nf][3] + by);
            }
        }
    }
}

// ============================================================
// Prep (single launch): x->fp16 cast, W_in/W_out transposes,
// and A [2048,16] -> Ah [16,2048] fp16.
// blocks [0,16384)        : cast x
// [16384, 20480)          : W_in  -> w1
// [20480, 22528)          : W_out -> w2
// [22528, 22656)          : A -> Ah
// ============================================================
__global__ __launch_bounds__(256) void prep_kernel(
    const float* __restrict__ x, __half* __restrict__ xs,
    const float* __restrict__ W_in, __half* __restrict__ w1,
    const float* __restrict__ W_out, __half* __restrict__ w2,
    const float* __restrict__ Amat, __half* __restrict__ Ah)
{
    __shared__ float t[32][33];
    const int b = blockIdx.x;
    const int tid = threadIdx.x;

    if (b < 16384) {                     // cast x (float4 per thread)
        const int idx = b * 256 + tid;
        const float4 v = ((const float4*)x)[idx];
        __half2* o = (__half2*)xs + idx * 2;
        o[0] = __floats2half2_rn(v.x, v.y);
        o[1] = __floats2half2_rn(v.z, v.w);
        return;
    }
    if (b >= 22528) {                    // A transpose (tiny)
        const int idx = (b - 22528) * 256 + tid;   // 0..32767
        const int s = idx >> 11;                   // 0..15
        const int e = idx & 2047;
        Ah[(size_t)s * EE + e] = __float2half(Amat[(size_t)e * DSTATE + s]);
        return;
    }

    const float* W;
    __half* Wt;
    int K, N, bx, by;
    if (b < 16384 + 4096) {
        const int bb = b - 16384;
        W = W_in; Wt = w1; K = DM; N = N1;
        bx = bb & 127; by = bb >> 7;
    } else {
        const int bb = b - 20480;
        W = W_out; Wt = w2; K = EE; N = DM;
        bx = bb & 31; by = bb >> 5;
    }
    const int k0 = by * 32;
    const int n0 = bx * 32;
    const int tx = tid & 31;
    const int ty = tid >> 5;

    for (int i = ty; i < 32; i += 8)
        t[i][tx] = W[(size_t)(k0 + i) * N + n0 + tx];
    __syncthreads();

    for (int i = ty; i < 32; i += 8)
        Wt[(size_t)(n0 + i) * K + k0 + tx] = __float2half(t[tx][i]);
}

// ============================================================
// Causal depthwise conv1d, k=4 — tiled, register rolling window.
// Writes fp32 xconv (for gated) AND fp16 xch (for u_mma).
// ============================================================
#define CBM 32
#define CBE 512

__global__ __launch_bounds__(256) void conv_kernel(
    const float* __restrict__ cw, const float* __restrict__ cb,
    const float* __restrict__ xp, float* __restrict__ xconv,
    __half* __restrict__ xch)
{
    const int t = threadIdx.x;
    const int c4 = t & 127;
    const int rg = t >> 7;
    const int e0 = blockIdx.x * CBE + c4 * 4;
    const int m0 = blockIdx.y * CBM + rg * 16;
    const int l0 = m0 & (LSEQ - 1);

    float w[4][4];
#pragma unroll
    for (int j = 0; j < 4; j++) {
        const float4 we = *(const float4*)(cw + (size_t)(e0 + j) * 4);
        w[0][j] = we.x; w[1][j] = we.y; w[2][j] = we.z; w[3][j] = we.w;
    }
    const float4 bias4 = *(const float4*)(cb + e0);

    const float* xrow = xp + (size_t)m0 * EE + e0;
    float* orow = xconv + (size_t)m0 * EE + e0;
    __half* hrow = xch + (size_t)m0 * EE + e0;

    float4 xm3, xm2, xm1;
    if (l0 == 0) {
        xm3 = xm2 = xm1 = make_float4(0.f, 0.f, 0.f, 0.f);
    } else {
        xm3 = *(const float4*)(xrow - (size_t)3 * EE);
        xm2 = *(const float4*)(xrow - (size_t)2 * EE);
        xm1 = *(const float4*)(xrow - (size_t)1 * EE);
    }

#pragma unroll
    for (int r = 0; r < 16; r++) {
        const float4 cur = *(const float4*)(xrow + (size_t)r * EE);
        float4 o;
        o.x = bias4.x + w[0][0]*xm3.x + w[1][0]*xm2.x + w[2][0]*xm1.x + w[3][0]*cur.x;
        o.y = bias4.y + w[0][1]*xm3.y + w[1][1]*xm2.y + w[2][1]*xm1.y + w[3][1]*cur.y;
        o.z = bias4.z + w[0][2]*xm3.z + w[1][2]*xm2.z + w[2][2]*xm1.z + w[3][2]*cur.z;
        o.w = bias4.w + w[0][3]*xm3.w + w[1][3]*xm2.w + w[2][3]*xm1.w + w[3][3]*cur.w;
        *(float4*)(orow + (size_t)r * EE) = o;
        st4h(hrow + (size_t)r * EE, o);
        xm3 = xm2; xm2 = xm1; xm1 = cur;
    }
}

// ============================================================
// u = xconv @ A via tensor cores.  u[M,16] fp32.
// A-operand: xch [M,2048] fp16; B-operand: Ah [16,2048] fp16,
// resident in smem (64 KB, 32 chunk-tiles of [16 x 64] swizzled).
// 128 rows/block, 8 warps (16 rows each), 3-stage cp.async.
// ============================================================
#define U_STAGE_BYTES (128 * ROWB)           // 16 KB
#define U_AH_BYTES    (DSTATE * EE * 2)      // 65536
#define U_SMEM_BYTES  (U_AH_BYTES + NSTAGE * U_STAGE_BYTES)  // 114688

__global__ __launch_bounds__(256, 1) void u_mma_kernel(
    const __half* __restrict__ X,   // xch [M, 2048]
    const __half* __restrict__ Ah,  // [16, 2048]
    float* __restrict__ u)
{
    extern __shared__ char dynsmem[];
    const uint32_t sbase = smem_u32(dynsmem);        // Ah tiles at base
    const uint32_t xbase = sbase + U_AH_BYTES;       // xconv stages

    const int tid = threadIdx.x;
    const int wid = tid >> 5;
    const int lane = tid & 31;
    const int bm = blockIdx.x * 128;

    // ---- stage Ah into smem: 4096 granules (n 0..15, kg 0..255)
    for (int idx = tid; idx < 4096; idx += 256) {
        const int n = idx & 15;
        const int kg = idx >> 4;            // global 16B-granule along K
        const int c = kg >> 3;              // chunk
        const int g = kg & 7;               // granule within chunk
        const uint4 v = *(const uint4*)(Ah + (size_t)n * EE + kg * 8);
        *(uint4*)(dynsmem + c * 2048 + swz(n, g)) = v;
    }

    // ---- xconv tile pipeline (identical mapping to mm_gemm A path)
    const int grow = tid >> 1;
    const int gg0 = (tid & 1) * 4;
    const __half* Xgl = X + (size_t)(bm + grow) * EE + gg0 * 8;
    uint32_t gdst[4];
#pragma unroll
    for (int i = 0; i < 4; i++) gdst[i] = swz(grow, gg0 + i);

    uint32_t sX[NSTAGE];
#pragma unroll
    for (int s = 0; s < NSTAGE; s++) sX[s] = xbase + s * U_STAGE_BYTES;

    float acc[2][4];
#pragma unroll
    for (int j = 0; j < 2; j++)
#pragma unroll
        for (int k = 0; k < 4; k++) acc[j][k] = 0.f;

    const int arow = wid * 16 + (lane & 15);
    const int axor = arow & 7;
    const int agl = lane >> 4;
    const int brow = (lane & 7) + ((lane >> 4) << 3);   // 0..15
    const int bxor = brow & 7;
    const int bgl = (lane >> 3) & 1;

    const int nchunk = EE / TBK;                        // 32

#pragma unroll
    for (int s = 0; s < NSTAGE - 1; s++) {
        const size_t koff = (size_t)s * TBK;
#pragma unroll
        for (int i = 0; i < 4; i++)
            CP_ASYNC_16(sX[s] + gdst[i], Xgl + koff + i * 8);
        CP_ASYNC_COMMIT();
    }
    __syncthreads();   // Ah staging complete before first ldmatrix

    int buf = 0, nbuf = NSTAGE - 1;
    for (int c = 0; c < nchunk; c++) {
        CP_ASYNC_WAIT1();
        __syncthreads();

        if (c + NSTAGE - 1 < nchunk) {
            const size_t koff = (size_t)(c + NSTAGE - 1) * TBK;
#pragma unroll
            for (int i = 0; i < 4; i++)
                CP_ASYNC_16(sX[nbuf] + gdst[i], Xgl + koff + i * 8);
        }
        CP_ASYNC_COMMIT();

#pragma unroll
        for (int ks = 0; ks < 4; ks++) {
            uint32_t af[4], bfr[2][2];
            {
                const uint32_t addr =
                    sX[buf] + arow * ROWB + (((ks * 2 + agl) ^ axor) << 4);
                ldm_x4(af[0], af[1], af[2], af[3], addr);
            }
            {
                const uint32_t addr =
                    sbase + c * 2048 + brow * ROWB + (((ks * 2 + bgl) ^ bxor) << 4);
                ldm_x4(bfr[0][0], bfr[0][1], bfr[1][0], bfr[1][1], addr);
            }
            mma_f16(acc[0], af, bfr[0]);
            mma_f16(acc[1], af, bfr[1]);
        }

        buf = (buf + 1 == NSTAGE) ? 0 : buf + 1;
        nbuf = (nbuf + 1 == NSTAGE) ? 0 : nbuf + 1;
    }

    // epilogue: u[row, col]
    const int erow = bm + wid * 16 + (lane >> 2);
    const int ecol = (lane & 3) * 2;
#pragma unroll
    for (int nf = 0; nf < 2; nf++) {
        float* U0 = u + (size_t)erow * DSTATE + ecol + nf * 8;
        float* U1 = U0 + (size_t)8 * DSTATE;
        *(float2*)U0 = make_float2(acc[nf][0], acc[nf][1]);
        *(float2*)U1 = make_float2(acc[nf][2], acc[nf][3]);
    }
}

// ============================================================
// Sequential scan h_t = tanh(u_t + h_{t-1}), hardware tanh.approx,
// 16-deep load prefetch. 64 independent chains.
// ============================================================
__global__ void scan_kernel(const float* __restrict__ u, float* __restrict__ h)
{
    const int b = threadIdx.x >> 4;
    const int s = threadIdx.x & 15;
    const float* up = u + (size_t)b * LSEQ * DSTATE + s;
    float* hp = h + (size_t)b * LSEQ * DSTATE + s;

    float buf[16], nxt[16];
#pragma unroll
    for (int i = 0; i < 16; i++) buf[i] = __ldg(up + (size_t)i * DSTATE);

    float hv = 0.f;
    for (int l0 = 0; l0 < LSEQ; l0 += 16) {
        if (l0 + 16 < LSEQ) {
#pragma unroll
            for (int i = 0; i < 16; i++)
                nxt[i] = __ldg(up + (size_t)(l0 + 16 + i) * DSTATE);
        }
#pragma unroll
        for (int i = 0; i < 16; i++) {
            hv += buf[i];
            asm("tanh.approx.f32 %0, %0;" : "+f"(hv));
            hp[(size_t)(l0 + i) * DSTATE] = hv;
        }
#pragma unroll
        for (int i = 0; i < 16; i++) buf[i] = nxt[i];
    }
}

// ============================================================
// gated = sigmoid(z) * (h @ C^T + Dp * xconv) -> fp16 [M, EE]
// ============================================================
__global__ __launch_bounds__(256) void gated_kernel(
    const float* __restrict__ Cmat, const float* __restrict__ Dp,
    const float* __restrict__ h, __half* __restrict__ gs)
{
    __shared__ float C_sh[256][17];
    __shared__ float h_sh[16][16];

    const int tid = threadIdx.x;
    const int e0 = blockIdx.x * 256;
    const int m0 = blockIdx.y * 16;

    {
        const float* crow = Cmat + (size_t)(e0 + tid) * DSTATE;
#pragma unroll
        for (int i = 0; i < DSTATE; i++) C_sh[tid][i] = crow[i];
    }
    ((float*)h_sh)[tid] = h[(size_t)m0 * DSTATE + tid];
    __syncthreads();

    const int e = e0 + tid;
    float creg[DSTATE];
#pragma unroll
    for (int i = 0; i < DSTATE; i++) creg[i] = C_sh[tid][i];
    const float dpe = Dp[e];

#pragma unroll
    for (int mi = 0; mi < 16; mi++) {
        const int m = m0 + mi;
        float dot = 0.f;
#pragma unroll
        for (int i = 0; i < DSTATE; i++) dot = fmaf(h_sh[mi][i], creg[i], dot);
        const float z = g_zp[(size_t)m * EE + e];
        const float xcv = g_xconv[(size_t)m * EE + e];
        const float sig = 1.f / (1.f + __expf(-z));
        gs[(size_t)m * EE + e] = __float2half(sig * (dot + dpe * xcv));
    }
}

// ============================================================
extern "C" void kernel_launch(void* const* d_in, const int* in_sizes, int n_in,
                              void* d_out, int out_size)
{
    const float* x      = (const float*)d_in[0];
    const float* W_in   = (const float*)d_in[1];
    const float* b_in   = (const float*)d_in[2];
    const float* conv_w = (const float*)d_in[3];
    const float* conv_b = (const float*)d_in[4];
    const float* Amat   = (const float*)d_in[5];
    const float* Cmat   = (const float*)d_in[6];
    const float* Dp     = (const float*)d_in[7];
    const float* W_out  = (const float*)d_in[8];
    const float* b_out  = (const float*)d_in[9];
    float* out = (float*)d_out;

    float* xp    = nullptr; cudaGetSymbolAddress((void**)&xp,    g_xp);
    float* zp    = nullptr; cudaGetSymbolAddress((void**)&zp,    g_zp);
    float* xconv = nullptr; cudaGetSymbolAddress((void**)&xconv, g_xconv);
    __half* xch  = nullptr; cudaGetSymbolAddress((void**)&xch,   g_xch);
    __half* Ah   = nullptr; cudaGetSymbolAddress((void**)&Ah,    g_Ah);
    float* u     = nullptr; cudaGetSymbolAddress((void**)&u,     g_u);
    float* h     = nullptr; cudaGetSymbolAddress((void**)&h,     g_h);
    __half* xs = nullptr; cudaGetSymbolAddress((void**)&xs, g_xs);
    __half* w1 = nullptr; cudaGetSymbolAddress((void**)&w1, g_w1);
    __half* gs = nullptr; cudaGetSymbolAddress((void**)&gs, g_gs);
    __half* w2 = nullptr; cudaGetSymbolAddress((void**)&w2, g_w2);

    cudaFuncSetAttribute(mm_gemm, cudaFuncAttributeMaxDynamicSharedMemorySize,
                         MM_SMEM_BYTES);
    cudaFuncSetAttribute(u_mma_kernel,
                         cudaFuncAttributeMaxDynamicSharedMemorySize,
                         U_SMEM_BYTES);

    // 0) prep: cast x + weight transposes + A transpose (single launch)
    prep_kernel<<<16384 + 4096 + 2048 + 128, 256>>>(x, xs, W_in, w1,
                                                    W_out, w2, Amat, Ah);

    // 1) [x_proj | z] = x @ W_in + b_in  (split epilogue, fp32 outs)
    {
        dim3 grid(N1 / TBN, M_TOTAL / TBM);
        mm_gemm<<<grid, 256, MM_SMEM_BYTES>>>(xs, w1, b_in, xp, zp,
                                              N1, KP1, 1);
    }

    // 2) causal depthwise conv (fp32 out + fp16 out)
    {
        dim3 grid(EE / CBE, M_TOTAL / CBM);
        conv_kernel<<<grid, 256>>>(conv_w, conv_b, xp, xconv, xch);
    }

    // 3) u = xconv @ A  (tensor-core mini-GEMM)
    u_mma_kernel<<<M_TOTAL / 128, 256, U_SMEM_BYTES>>>(xch, Ah, u);

    // 4) sequential tanh scan
    scan_kernel<<<1, BATCH * DSTATE>>>(u, h);

    // 5) gated (writes fp16)
    {
        dim3 grid(EE / 256, M_TOTAL / 16);
        gated_kernel<<<grid, 256>>>(Cmat, Dp, h, gs);
    }

    // 6) out = gated @ W_out + b_out  (fp16, K = 2048, fp32 out)
    {
        dim3 grid(DM / TBN, M_TOTAL / TBM);
        mm_gemm<<<grid, 256, MM_SMEM_BYTES>>>(gs, w2, b_out, out, nullptr,
                                              DM, KP2, 0);
    }
}